// round 1
// baseline (speedup 1.0000x reference)
#include <cuda_runtime.h>
#include <math.h>

#define DIMQ 8
#define TRILQ 36
#define SEQ 10
#define NSWEEPS 7

__device__ __forceinline__ constexpr int tix(int i, int j) { return i * (i + 1) / 2 + j; } // j<=i

__global__ __launch_bounds__(64) void qcbow_kernel(
    const int* __restrict__ contexts,
    const int* __restrict__ targets,
    const float* __restrict__ emb,
    float* __restrict__ out, int B)
{
    int b = blockIdx.x * blockDim.x + threadIdx.x;
    if (b >= B) return;

    float acc[TRILQ];
#pragma unroll
    for (int i = 0; i < TRILQ; i++) acc[i] = 0.f;
    float cnt = 0.f;
    float sig[TRILQ];

    // tokens 0..9 = context, 10 = target
#pragma unroll 1
    for (int s = 0; s <= SEQ; s++) {
        int tok = (s < SEQ) ? contexts[b * SEQ + s] : targets[b];
        const float* row = emb + (long)tok * TRILQ;
        float L[TRILQ];
#pragma unroll
        for (int i = 0; i < TRILQ; i++) L[i] = __ldg(row + i);
        // clamp diagonal >= 1e-4
#pragma unroll
        for (int i = 0; i < DIMQ; i++) {
            int d = tix(i, i);
            L[d] = fmaxf(L[d], 1e-4f);
        }
        // P = L L^T (lower tri), trace
        float P[TRILQ];
        float tr = 0.f;
#pragma unroll
        for (int i = 0; i < DIMQ; i++) {
#pragma unroll
            for (int j = 0; j <= i; j++) {
                float sm = 0.f;
#pragma unroll
                for (int k = 0; k <= j; k++)
                    sm = fmaf(L[tix(i, k)], L[tix(j, k)], sm);
                P[tix(i, j)] = sm;
                if (i == j) tr += sm;
            }
        }
        // density = (P + 2e-6 I) / (tr(P) + 1.6e-5 + 1e-6)
        float inv = 1.0f / (tr + 1.7e-5f);
        if (s < SEQ) {
            if (tok != 0) {
                cnt += 1.f;
#pragma unroll
                for (int i = 0; i < DIMQ; i++)
#pragma unroll
                    for (int j = 0; j <= i; j++) {
                        float v = P[tix(i, j)] + ((i == j) ? 2e-6f : 0.f);
                        acc[tix(i, j)] = fmaf(v, inv, acc[tix(i, j)]);
                    }
            }
        } else {
#pragma unroll
            for (int i = 0; i < DIMQ; i++)
#pragma unroll
                for (int j = 0; j <= i; j++) {
                    float v = P[tix(i, j)] + ((i == j) ? 2e-6f : 0.f);
                    sig[tix(i, j)] = v * inv;
                }
        }
    }

    float icnt = 1.0f / cnt;

    // rho' = ctx_avg + 1e-6 I ; Cholesky in place: C C^T = rho'
    float C[TRILQ];
#pragma unroll
    for (int t = 0; t < TRILQ; t++) C[t] = acc[t] * icnt;
#pragma unroll
    for (int i = 0; i < DIMQ; i++) C[tix(i, i)] += 1e-6f;

#pragma unroll
    for (int j = 0; j < DIMQ; j++) {
        float d = C[tix(j, j)];
#pragma unroll
        for (int k = 0; k < j; k++) d = fmaf(-C[tix(j, k)], C[tix(j, k)], d);
        d = sqrtf(fmaxf(d, 1e-14f));
        C[tix(j, j)] = d;
        float invd = 1.0f / d;
#pragma unroll
        for (int i = j + 1; i < DIMQ; i++) {
            float v = C[tix(i, j)];
#pragma unroll
            for (int k = 0; k < j; k++) v = fmaf(-C[tix(i, k)], C[tix(j, k)], v);
            C[tix(i, j)] = v * invd;
        }
    }

    // M = C^T * sigma * C  (symmetric); eig(M) == eig(sqrt(rho') sigma sqrt(rho'))
    float M[DIMQ][DIMQ];
#pragma unroll
    for (int j = 0; j < DIMQ; j++) {
        float v[DIMQ];
#pragma unroll
        for (int a = 0; a < DIMQ; a++) {
            float sm = 0.f;
#pragma unroll
            for (int bb = j; bb < DIMQ; bb++) {
                float sab = (a >= bb) ? sig[tix(a, bb)] : sig[tix(bb, a)];
                sm = fmaf(sab, C[tix(bb, j)], sm);
            }
            v[a] = sm;
        }
#pragma unroll
        for (int i = 0; i <= j; i++) {
            float sm = 0.f;
#pragma unroll
            for (int a = i; a < DIMQ; a++)
                sm = fmaf(C[tix(a, i)], v[a], sm);
            M[i][j] = sm;
            M[j][i] = sm;
        }
    }

    // Cyclic Jacobi, eigenvalues only
#pragma unroll 1
    for (int sweep = 0; sweep < NSWEEPS; sweep++) {
#pragma unroll
        for (int p = 0; p < DIMQ - 1; p++) {
#pragma unroll
            for (int q = p + 1; q < DIMQ; q++) {
                float apq = M[p][q];
                if (fabsf(apq) > 1e-14f) {
                    float app = M[p][p], aqq = M[q][q];
                    float theta = (aqq - app) / (2.f * apq);
                    float t = 1.0f / (fabsf(theta) + sqrtf(fmaf(theta, theta, 1.f)));
                    if (theta < 0.f) t = -t;
                    float c = rsqrtf(fmaf(t, t, 1.f));
                    float ss = t * c;
                    // A <- J^T A J  (rows then cols)
#pragma unroll
                    for (int k = 0; k < DIMQ; k++) {
                        float apk = M[p][k], aqk = M[q][k];
                        M[p][k] = c * apk - ss * aqk;
                        M[q][k] = ss * apk + c * aqk;
                    }
#pragma unroll
                    for (int k = 0; k < DIMQ; k++) {
                        float akp = M[k][p], akq = M[k][q];
                        M[k][p] = c * akp - ss * akq;
                        M[k][q] = ss * akp + c * akq;
                    }
                }
            }
        }
    }

    float f = 0.f;
#pragma unroll
    for (int i = 0; i < DIMQ; i++) f += sqrtf(fabsf(M[i][i]) + 1e-6f);
    f = fminf(fmaxf(f, 0.f), 1.f);
    out[b] = -logf(fmaxf(f, 1e-8f));
}

extern "C" void kernel_launch(void* const* d_in, const int* in_sizes, int n_in,
                              void* d_out, int out_size) {
    const int* contexts = (const int*)d_in[0];
    const int* targets  = (const int*)d_in[1];
    const float* emb    = (const float*)d_in[2];
    float* out = (float*)d_out;
    int B = in_sizes[1]; // number of targets = batch size
    int threads = 64;
    int blocks = (B + threads - 1) / threads;
    qcbow_kernel<<<blocks, threads>>>(contexts, targets, emb, out, B);
}

// round 2
// speedup vs baseline: 1.1311x; 1.1311x over previous
#include <cuda_runtime.h>
#include <math.h>

#define DIMQ 8
#define TRILQ 36
#define SEQ 10
#define NSWEEPS 5
#define FULLM 0xffffffffu

__device__ __forceinline__ constexpr int tix(int i, int j) { return i * (i + 1) / 2 + j; } // j<=i

__device__ __forceinline__ float sel4(float a, float b, float c, float d, int u) {
    float ab = (u & 1) ? b : a;
    float cd = (u & 1) ? d : c;
    return (u & 2) ? cd : ab;
}

// Compute density of one token's L and fold into dst.
// accumulate: dst += density ; else dst = density. gate=false => contribute 0.
__device__ __forceinline__ void accum_density(const float* __restrict__ row,
                                              float* dst, bool accumulate, bool gate) {
    float L[TRILQ];
    const float4* r4 = (const float4*)row;
#pragma unroll
    for (int q = 0; q < 9; q++) {
        float4 v = __ldg(r4 + q);
        L[4 * q + 0] = v.x; L[4 * q + 1] = v.y; L[4 * q + 2] = v.z; L[4 * q + 3] = v.w;
    }
#pragma unroll
    for (int i = 0; i < DIMQ; i++) L[tix(i, i)] = fmaxf(L[tix(i, i)], 1e-4f);
    // tr(L L^T) = ||L||_F^2
    float tr = 0.f;
#pragma unroll
    for (int t = 0; t < TRILQ; t++) tr = fmaf(L[t], L[t], tr);
    // rho = L L^T + 2e-6 I (analytic: eig-shift corr is exactly 1e-6); denom = tr + 16e-6 + 1e-6
    float inv = gate ? (1.0f / (tr + 1.7e-5f)) : 0.f;
#pragma unroll
    for (int i = 0; i < DIMQ; i++)
#pragma unroll
        for (int j = 0; j <= i; j++) {
            float sm = (i == j) ? 2e-6f : 0.f;
#pragma unroll
            for (int k = 0; k <= j; k++)
                sm = fmaf(L[tix(i, k)], L[tix(j, k)], sm);
            if (accumulate) dst[tix(i, j)] = fmaf(sm, inv, dst[tix(i, j)]);
            else            dst[tix(i, j)] = sm * inv;
        }
}

__global__ __launch_bounds__(256, 2) void qcbow_kernel(
    const int* __restrict__ contexts,
    const int* __restrict__ targets,
    const float* __restrict__ emb,
    float* __restrict__ out, int B)
{
    int tid = blockIdx.x * blockDim.x + threadIdx.x;
    int b = tid >> 2;       // element
    int u = tid & 3;        // lane within quad
    if (b >= B) return;

    float acc[TRILQ];
#pragma unroll
    for (int t = 0; t < TRILQ; t++) acc[t] = 0.f;
    float sig[TRILQ];
#pragma unroll
    for (int t = 0; t < TRILQ; t++) sig[t] = 0.f;
    float cnt = 0.f;

    // ---- Phase 1: token densities, split across the quad ----
#pragma unroll
    for (int r = 0; r < 3; r++) {
        int s = u + r * 4;
        if (s < SEQ) {
            int tok = __ldg(contexts + b * SEQ + s);
            bool gate = (tok != 0);
            accum_density(emb + (size_t)tok * TRILQ, acc, true, gate);
            cnt += gate ? 1.f : 0.f;
        }
    }
    if (u == 3) {
        int tok = __ldg(targets + b);
        accum_density(emb + (size_t)tok * TRILQ, sig, false, true);
    }

    // quad all-reduce of acc, cnt; broadcast sig from lane 3
#pragma unroll
    for (int t = 0; t < TRILQ; t++) {
        acc[t] += __shfl_xor_sync(FULLM, acc[t], 1, 4);
        acc[t] += __shfl_xor_sync(FULLM, acc[t], 2, 4);
    }
    cnt += __shfl_xor_sync(FULLM, cnt, 1, 4);
    cnt += __shfl_xor_sync(FULLM, cnt, 2, 4);
#pragma unroll
    for (int t = 0; t < TRILQ; t++) sig[t] = __shfl_sync(FULLM, sig[t], 3, 4);

    // ---- rho' = ctx_avg + 1e-6 I ; Cholesky in place (redundant per lane) ----
    float icnt = 1.0f / cnt;
#pragma unroll
    for (int t = 0; t < TRILQ; t++) acc[t] *= icnt;
#pragma unroll
    for (int i = 0; i < DIMQ; i++) acc[tix(i, i)] += 1e-6f;

#pragma unroll
    for (int j = 0; j < DIMQ; j++) {
        float d = acc[tix(j, j)];
#pragma unroll
        for (int k = 0; k < j; k++) d = fmaf(-acc[tix(j, k)], acc[tix(j, k)], d);
        d = sqrtf(fmaxf(d, 1e-20f));
        acc[tix(j, j)] = d;
        float invd = 1.0f / d;
#pragma unroll
        for (int i = j + 1; i < DIMQ; i++) {
            float v = acc[tix(i, j)];
#pragma unroll
            for (int k = 0; k < j; k++) v = fmaf(-acc[tix(i, k)], acc[tix(j, k)], v);
            acc[tix(i, j)] = v * invd;
        }
    }

    // ---- columns u and 4+u of C (static indices + 4-way select) ----
    float cu[DIMQ], cv[DIMQ];
#pragma unroll
    for (int a = 0; a < DIMQ; a++) {
        float x0 =            acc[tix(a, 0)];
        float x1 = (a >= 1) ? acc[tix(a, 1)] : 0.f;
        float x2 = (a >= 2) ? acc[tix(a, 2)] : 0.f;
        float x3 = (a >= 3) ? acc[tix(a, 3)] : 0.f;
        cu[a] = sel4(x0, x1, x2, x3, u);
        float y0 = (a >= 4) ? acc[tix(a, 4)] : 0.f;
        float y1 = (a >= 5) ? acc[tix(a, 5)] : 0.f;
        float y2 = (a >= 6) ? acc[tix(a, 6)] : 0.f;
        float y3 = (a >= 7) ? acc[tix(a, 7)] : 0.f;
        cv[a] = sel4(y0, y1, y2, y3, u);
    }

    // ---- M = C^T sigma C ; this lane keeps rows u (T) and 4+u (Bw) ----
    float T[DIMQ], Bw[DIMQ];
#pragma unroll
    for (int j = 0; j < DIMQ; j++) {
        float w[DIMQ];
#pragma unroll
        for (int a = 0; a < DIMQ; a++) {
            float sm = 0.f;
#pragma unroll
            for (int bb = j; bb < DIMQ; bb++) {
                float sab = (a >= bb) ? sig[tix(a, bb)] : sig[tix(bb, a)];
                sm = fmaf(sab, acc[tix(bb, j)], sm);
            }
            w[a] = sm;
        }
        float tj = 0.f, bj = 0.f;
#pragma unroll
        for (int a = 0; a < DIMQ; a++) {
            tj = fmaf(cu[a], w[a], tj);
            bj = fmaf(cv[a], w[a], bj);
        }
        T[j] = tj; Bw[j] = bj;
    }

    // ---- Parallel two-sided Jacobi (Brent-Luk tournament, position space) ----
    // Pairs are always (pos u, pos 4+u). Per-round position permutation:
    // new[0..7] = old[0,4,1,2,5,6,7,3]  (order-7 cycle => 7 rounds = full sweep)
#pragma unroll 1
    for (int sweep = 0; sweep < NSWEEPS; sweep++) {
#pragma unroll
        for (int round = 0; round < 7; round++) {
            float app = sel4(T[0], T[1], T[2], T[3], u);
            float apq = sel4(T[4], T[5], T[6], T[7], u);
            float aqq = sel4(Bw[4], Bw[5], Bw[6], Bw[7], u);
            float theta = (aqq - app) / (2.f * apq);
            float tt = 1.0f / (fabsf(theta) + sqrtf(fmaf(theta, theta, 1.f)));
            tt = (theta < 0.f) ? -tt : tt;
            float c = rsqrtf(fmaf(tt, tt, 1.f));
            float s = tt * c;
            bool ok = fabsf(apq) > 1e-20f;
            c = ok ? c : 1.f;
            s = ok ? s : 0.f;
            float cs[4], ss[4];
#pragma unroll
            for (int i = 0; i < 4; i++) {
                cs[i] = __shfl_sync(FULLM, c, i, 4);
                ss[i] = __shfl_sync(FULLM, s, i, 4);
            }
            // left transform: rows u and 4+u with own rotation
#pragma unroll
            for (int k = 0; k < DIMQ; k++) {
                float t0 = T[k], b0 = Bw[k];
                T[k]  = c * t0 - s * b0;
                Bw[k] = s * t0 + c * b0;
            }
            // right transform: columns (i, 4+i) with each broadcast rotation
#pragma unroll
            for (int i = 0; i < 4; i++) {
                float tp = T[i], tq = T[4 + i];
                T[i]     = cs[i] * tp - ss[i] * tq;
                T[4 + i] = ss[i] * tp + cs[i] * tq;
                float bp = Bw[i], bq = Bw[4 + i];
                Bw[i]     = cs[i] * bp - ss[i] * bq;
                Bw[4 + i] = ss[i] * bp + cs[i] * bq;
            }
            // row migration: newT_u <- (u==0? keep : lane u-1's (u-1==0? B : T));
            //                newB_u <- (u==3? own old T : lane u+1's B)
            int srcT = (u == 0) ? 0 : (u - 1);
            int srcB = (u == 3) ? 3 : (u + 1);
            float nT[DIMQ], nB[DIMQ];
#pragma unroll
            for (int k = 0; k < DIMQ; k++) {
                float offT = (u == 0) ? Bw[k] : T[k];
                float rT = __shfl_sync(FULLM, offT, srcT, 4);
                nT[k] = (u == 0) ? T[k] : rT;
                float rB = __shfl_sync(FULLM, Bw[k], srcB, 4);
                nB[k] = (u == 3) ? T[k] : rB;
            }
            // column permutation (register renaming): new[k] = old[perm[k]], perm = {0,4,1,2,5,6,7,3}
            T[0] = nT[0]; T[1] = nT[4]; T[2] = nT[1]; T[3] = nT[2];
            T[4] = nT[5]; T[5] = nT[6]; T[6] = nT[7]; T[7] = nT[3];
            Bw[0] = nB[0]; Bw[1] = nB[4]; Bw[2] = nB[1]; Bw[3] = nB[2];
            Bw[4] = nB[5]; Bw[5] = nB[6]; Bw[6] = nB[7]; Bw[7] = nB[3];
        }
    }

    // diag entries of this lane's rows: (pos u, col u) and (pos 4+u, col 4+u)
    float d1 = sel4(T[0], T[1], T[2], T[3], u);
    float d2 = sel4(Bw[4], Bw[5], Bw[6], Bw[7], u);
    float f = sqrtf(fabsf(d1) + 1e-6f) + sqrtf(fabsf(d2) + 1e-6f);
    f += __shfl_xor_sync(FULLM, f, 1, 4);
    f += __shfl_xor_sync(FULLM, f, 2, 4);
    if (u == 0) {
        f = fminf(fmaxf(f, 0.f), 1.f);
        out[b] = -logf(fmaxf(f, 1e-8f));
    }
}

extern "C" void kernel_launch(void* const* d_in, const int* in_sizes, int n_in,
                              void* d_out, int out_size) {
    const int* contexts = (const int*)d_in[0];
    const int* targets  = (const int*)d_in[1];
    const float* emb    = (const float*)d_in[2];
    float* out = (float*)d_out;
    int B = in_sizes[1];
    int threads = 256;
    int total = B * 4;
    int blocks = (total + threads - 1) / threads;
    qcbow_kernel<<<blocks, threads>>>(contexts, targets, emb, out, B);
}

// round 5
// speedup vs baseline: 1.3174x; 1.1648x over previous
#include <cuda_runtime.h>
#include <math.h>

#define DIMQ 8
#define TRILQ 36
#define SEQ 10
#define NSWEEPS 3
#define FULLM 0xffffffffu

__device__ __forceinline__ constexpr int tix(int i, int j) { return i * (i + 1) / 2 + j; } // j<=i

__device__ __forceinline__ float sel4(float a, float b, float c, float d, int u) {
    float ab = (u & 1) ? b : a;
    float cd = (u & 1) ? d : c;
    return (u & 2) ? cd : ab;
}

// Compute density of one token's L and fold into dst.
// accumulate: dst += density ; else dst = density. gate=false => contribute 0.
__device__ __forceinline__ void accum_density(const float* __restrict__ row,
                                              float* dst, bool accumulate, bool gate) {
    float L[TRILQ];
    const float4* r4 = (const float4*)row;
#pragma unroll
    for (int q = 0; q < 9; q++) {
        float4 v = __ldg(r4 + q);
        L[4 * q + 0] = v.x; L[4 * q + 1] = v.y; L[4 * q + 2] = v.z; L[4 * q + 3] = v.w;
    }
#pragma unroll
    for (int i = 0; i < DIMQ; i++) L[tix(i, i)] = fmaxf(L[tix(i, i)], 1e-4f);
    // tr(L L^T) = ||L||_F^2
    float tr = 0.f;
#pragma unroll
    for (int t = 0; t < TRILQ; t++) tr = fmaf(L[t], L[t], tr);
    // rho = L L^T + 2e-6 I (analytic: eig-shift corr is exactly 1e-6); denom = tr + 16e-6 + 1e-6
    float inv = gate ? (1.0f / (tr + 1.7e-5f)) : 0.f;
#pragma unroll
    for (int i = 0; i < DIMQ; i++)
#pragma unroll
        for (int j = 0; j <= i; j++) {
            float sm = (i == j) ? 2e-6f : 0.f;
#pragma unroll
            for (int k = 0; k <= j; k++)
                sm = fmaf(L[tix(i, k)], L[tix(j, k)], sm);
            if (accumulate) dst[tix(i, j)] = fmaf(sm, inv, dst[tix(i, j)]);
            else            dst[tix(i, j)] = sm * inv;
        }
}

__global__ __launch_bounds__(256, 2) void qcbow_kernel(
    const int* __restrict__ contexts,
    const int* __restrict__ targets,
    const float* __restrict__ emb,
    float* __restrict__ out, int B)
{
    int tid = blockIdx.x * blockDim.x + threadIdx.x;
    int b = tid >> 2;       // element
    int u = tid & 3;        // lane within quad
    if (b >= B) return;

    float acc[TRILQ];
#pragma unroll
    for (int t = 0; t < TRILQ; t++) acc[t] = 0.f;
    float sig[TRILQ];
#pragma unroll
    for (int t = 0; t < TRILQ; t++) sig[t] = 0.f;
    float cnt = 0.f;

    // ---- Phase 1: token densities, split across the quad ----
#pragma unroll
    for (int r = 0; r < 3; r++) {
        int s = u + r * 4;
        if (s < SEQ) {
            int tok = __ldg(contexts + b * SEQ + s);
            bool gate = (tok != 0);
            accum_density(emb + (size_t)tok * TRILQ, acc, true, gate);
            cnt += gate ? 1.f : 0.f;
        }
    }
    if (u == 3) {
        int tok = __ldg(targets + b);
        accum_density(emb + (size_t)tok * TRILQ, sig, false, true);
    }

    // quad all-reduce of acc, cnt; broadcast sig from lane 3
#pragma unroll
    for (int t = 0; t < TRILQ; t++) {
        acc[t] += __shfl_xor_sync(FULLM, acc[t], 1, 4);
        acc[t] += __shfl_xor_sync(FULLM, acc[t], 2, 4);
    }
    cnt += __shfl_xor_sync(FULLM, cnt, 1, 4);
    cnt += __shfl_xor_sync(FULLM, cnt, 2, 4);
#pragma unroll
    for (int t = 0; t < TRILQ; t++) sig[t] = __shfl_sync(FULLM, sig[t], 3, 4);

    // ---- rho' = ctx_avg + 1e-6 I ; Cholesky in place (redundant per lane) ----
    float icnt = 1.0f / cnt;
#pragma unroll
    for (int t = 0; t < TRILQ; t++) acc[t] *= icnt;
#pragma unroll
    for (int i = 0; i < DIMQ; i++) acc[tix(i, i)] += 1e-6f;

#pragma unroll
    for (int j = 0; j < DIMQ; j++) {
        float d = acc[tix(j, j)];
#pragma unroll
        for (int k = 0; k < j; k++) d = fmaf(-acc[tix(j, k)], acc[tix(j, k)], d);
        d = sqrtf(fmaxf(d, 1e-20f));
        acc[tix(j, j)] = d;
        float invd = 1.0f / d;
#pragma unroll
        for (int i = j + 1; i < DIMQ; i++) {
            float v = acc[tix(i, j)];
#pragma unroll
            for (int k = 0; k < j; k++) v = fmaf(-acc[tix(i, k)], acc[tix(j, k)], v);
            acc[tix(i, j)] = v * invd;
        }
    }

    // ---- columns u and 4+u of C (static indices + 4-way select) ----
    float cu[DIMQ], cv[DIMQ];
#pragma unroll
    for (int a = 0; a < DIMQ; a++) {
        float x0 =            acc[tix(a, 0)];
        float x1 = (a >= 1) ? acc[tix(a, 1)] : 0.f;
        float x2 = (a >= 2) ? acc[tix(a, 2)] : 0.f;
        float x3 = (a >= 3) ? acc[tix(a, 3)] : 0.f;
        cu[a] = sel4(x0, x1, x2, x3, u);
        float y0 = (a >= 4) ? acc[tix(a, 4)] : 0.f;
        float y1 = (a >= 5) ? acc[tix(a, 5)] : 0.f;
        float y2 = (a >= 6) ? acc[tix(a, 6)] : 0.f;
        float y3 = (a >= 7) ? acc[tix(a, 7)] : 0.f;
        cv[a] = sel4(y0, y1, y2, y3, u);
    }

    // ---- Rows u (T) and 4+u (Bw) of M = C^T sigma C, via symmetry:
    //      M[u][j] = sum_b C[b][j] * (sigma C[:,u])[b]   (~200 fma/lane, no redundancy)
    float T[DIMQ], Bw[DIMQ];
    {
        float wu[DIMQ], wv[DIMQ];
#pragma unroll
        for (int a = 0; a < DIMQ; a++) {
            float su = 0.f, sv = 0.f;
#pragma unroll
            for (int bb = 0; bb < DIMQ; bb++) {
                float sab = (a >= bb) ? sig[tix(a, bb)] : sig[tix(bb, a)];
                su = fmaf(sab, cu[bb], su);
                sv = fmaf(sab, cv[bb], sv);
            }
            wu[a] = su; wv[a] = sv;
        }
#pragma unroll
        for (int j = 0; j < DIMQ; j++) {
            float tj = 0.f, bj = 0.f;
#pragma unroll
            for (int a = j; a < DIMQ; a++) {
                float caj = acc[tix(a, j)];
                tj = fmaf(caj, wu[a], tj);
                bj = fmaf(caj, wv[a], bj);
            }
            T[j] = tj; Bw[j] = bj;
        }
    }

    // ---- Parallel two-sided Jacobi (Brent-Luk tournament, position space) ----
    // Pairs are always (pos u, pos 4+u). Per-round position permutation:
    // new[0..7] = old[0,4,1,2,5,6,7,3]  (order-7 cycle => 7 rounds = full sweep)
#pragma unroll 1
    for (int sweep = 0; sweep < NSWEEPS; sweep++) {
#pragma unroll
        for (int round = 0; round < 7; round++) {
            float app = sel4(T[0], T[1], T[2], T[3], u);
            float apq = sel4(T[4], T[5], T[6], T[7], u);
            float aqq = sel4(Bw[4], Bw[5], Bw[6], Bw[7], u);
            float theta = (aqq - app) / (2.f * apq);
            float tt = 1.0f / (fabsf(theta) + sqrtf(fmaf(theta, theta, 1.f)));
            tt = (theta < 0.f) ? -tt : tt;
            float c = rsqrtf(fmaf(tt, tt, 1.f));
            float s = tt * c;
            bool ok = fabsf(apq) > 1e-20f;
            c = ok ? c : 1.f;
            s = ok ? s : 0.f;
            float cs[4], ss[4];
#pragma unroll
            for (int i = 0; i < 4; i++) {
                cs[i] = __shfl_sync(FULLM, c, i, 4);
                ss[i] = __shfl_sync(FULLM, s, i, 4);
            }
            // left transform: rows u and 4+u with own rotation
#pragma unroll
            for (int k = 0; k < DIMQ; k++) {
                float t0 = T[k], b0 = Bw[k];
                T[k]  = c * t0 - s * b0;
                Bw[k] = s * t0 + c * b0;
            }
            // right transform: columns (i, 4+i) with each broadcast rotation
#pragma unroll
            for (int i = 0; i < 4; i++) {
                float tp = T[i], tq = T[4 + i];
                T[i]     = cs[i] * tp - ss[i] * tq;
                T[4 + i] = ss[i] * tp + cs[i] * tq;
                float bp = Bw[i], bq = Bw[4 + i];
                Bw[i]     = cs[i] * bp - ss[i] * bq;
                Bw[4 + i] = ss[i] * bp + cs[i] * bq;
            }
            // row migration: newT_u <- (u==0? keep : lane u-1's (u-1==0? B : T));
            //                newB_u <- (u==3? own old T : lane u+1's B)
            int srcT = (u == 0) ? 0 : (u - 1);
            int srcB = (u == 3) ? 3 : (u + 1);
            float nT[DIMQ], nB[DIMQ];
#pragma unroll
            for (int k = 0; k < DIMQ; k++) {
                float offT = (u == 0) ? Bw[k] : T[k];
                float rT = __shfl_sync(FULLM, offT, srcT, 4);
                nT[k] = (u == 0) ? T[k] : rT;
                float rB = __shfl_sync(FULLM, Bw[k], srcB, 4);
                nB[k] = (u == 3) ? T[k] : rB;
            }
            // column permutation (register renaming): new[k] = old[perm[k]], perm = {0,4,1,2,5,6,7,3}
            T[0] = nT[0]; T[1] = nT[4]; T[2] = nT[1]; T[3] = nT[2];
            T[4] = nT[5]; T[5] = nT[6]; T[6] = nT[7]; T[7] = nT[3];
            Bw[0] = nB[0]; Bw[1] = nB[4]; Bw[2] = nB[1]; Bw[3] = nB[2];
            Bw[4] = nB[5]; Bw[5] = nB[6]; Bw[6] = nB[7]; Bw[7] = nB[3];
        }
    }

    // diag entries of this lane's rows: (pos u, col u) and (pos 4+u, col 4+u)
    float d1 = sel4(T[0], T[1], T[2], T[3], u);
    float d2 = sel4(Bw[4], Bw[5], Bw[6], Bw[7], u);
    float f = sqrtf(fabsf(d1) + 1e-6f) + sqrtf(fabsf(d2) + 1e-6f);
    f += __shfl_xor_sync(FULLM, f, 1, 4);
    f += __shfl_xor_sync(FULLM, f, 2, 4);
    if (u == 0) {
        f = fminf(fmaxf(f, 0.f), 1.f);
        out[b] = -logf(fmaxf(f, 1e-8f));
    }
}

extern "C" void kernel_launch(void* const* d_in, const int* in_sizes, int n_in,
                              void* d_out, int out_size) {
    const int* contexts = (const int*)d_in[0];
    const int* targets  = (const int*)d_in[1];
    const float* emb    = (const float*)d_in[2];
    float* out = (float*)d_out;
    int B = in_sizes[1];
    int threads = 256;
    int total = B * 4;
    int blocks = (total + threads - 1) / threads;
    qcbow_kernel<<<blocks, threads>>>(contexts, targets, emb, out, B);
}

// round 10
// speedup vs baseline: 2.0619x; 1.5651x over previous
#include <cuda_runtime.h>
#include <math.h>

#define DIMQ 8
#define TRILQ 36
#define SEQ 10
#define NROUNDS 17   // 2.43 tournament sweeps (7 rounds = 1 sweep); 21 was converged w/ margin
#define FULLM 0xffffffffu

__device__ __forceinline__ constexpr int tix(int i, int j) { return i * (i + 1) / 2 + j; } // j<=i

__device__ __forceinline__ float sel4(float a, float b, float c, float d, int u) {
    float ab = (u & 1) ? b : a;
    float cd = (u & 1) ? d : c;
    return (u & 2) ? cd : ab;
}

// Compute density of one token's L and fold into dst.
__device__ __forceinline__ void accum_density(const float* __restrict__ row,
                                              float* dst, bool accumulate, bool gate) {
    float L[TRILQ];
    const float4* r4 = (const float4*)row;
#pragma unroll
    for (int q = 0; q < 9; q++) {
        float4 v = __ldg(r4 + q);
        L[4 * q + 0] = v.x; L[4 * q + 1] = v.y; L[4 * q + 2] = v.z; L[4 * q + 3] = v.w;
    }
#pragma unroll
    for (int i = 0; i < DIMQ; i++) L[tix(i, i)] = fmaxf(L[tix(i, i)], 1e-4f);
    float tr = 0.f;
#pragma unroll
    for (int t = 0; t < TRILQ; t++) tr = fmaf(L[t], L[t], tr);
    // analytic: eig-shift corr is exactly 1e-6 -> rho = L L^T + 2e-6 I, denom = tr + 1.7e-5
    float inv = gate ? (1.0f / (tr + 1.7e-5f)) : 0.f;
#pragma unroll
    for (int i = 0; i < DIMQ; i++)
#pragma unroll
        for (int j = 0; j <= i; j++) {
            float sm = (i == j) ? 2e-6f : 0.f;
#pragma unroll
            for (int k = 0; k <= j; k++)
                sm = fmaf(L[tix(i, k)], L[tix(j, k)], sm);
            if (accumulate) dst[tix(i, j)] = fmaf(sm, inv, dst[tix(i, j)]);
            else            dst[tix(i, j)] = sm * inv;
        }
}

__global__ __launch_bounds__(64, 8) void qcbow_kernel(
    const int* __restrict__ contexts,
    const int* __restrict__ targets,
    const float* __restrict__ emb,
    float* __restrict__ out, int B)
{
    int tid = blockIdx.x * blockDim.x + threadIdx.x;
    int b = tid >> 2;       // element
    int u = tid & 3;        // lane within quad
    if (b >= B) return;

    float acc[TRILQ];
#pragma unroll
    for (int t = 0; t < TRILQ; t++) acc[t] = 0.f;
    float sig[TRILQ];
#pragma unroll
    for (int t = 0; t < TRILQ; t++) sig[t] = 0.f;
    float cnt = 0.f;

    // ---- Phase 1: token densities, split across the quad ----
#pragma unroll
    for (int r = 0; r < 3; r++) {
        int s = u + r * 4;
        if (s < SEQ) {
            int tok = __ldg(contexts + b * SEQ + s);
            bool gate = (tok != 0);
            accum_density(emb + (size_t)tok * TRILQ, acc, true, gate);
            cnt += gate ? 1.f : 0.f;
        }
    }
    if (u == 3) {
        int tok = __ldg(targets + b);
        accum_density(emb + (size_t)tok * TRILQ, sig, false, true);
    }

    // quad all-reduce of acc, cnt; broadcast sig from lane 3
#pragma unroll
    for (int t = 0; t < TRILQ; t++) {
        acc[t] += __shfl_xor_sync(FULLM, acc[t], 1, 4);
        acc[t] += __shfl_xor_sync(FULLM, acc[t], 2, 4);
    }
    cnt += __shfl_xor_sync(FULLM, cnt, 1, 4);
    cnt += __shfl_xor_sync(FULLM, cnt, 2, 4);
#pragma unroll
    for (int t = 0; t < TRILQ; t++) sig[t] = __shfl_sync(FULLM, sig[t], 3, 4);

    // ---- rho' = ctx_avg + 1e-6 I ; Cholesky in place (redundant per lane) ----
    float icnt = 1.0f / cnt;
#pragma unroll
    for (int t = 0; t < TRILQ; t++) acc[t] *= icnt;
#pragma unroll
    for (int i = 0; i < DIMQ; i++) acc[tix(i, i)] += 1e-6f;

#pragma unroll
    for (int j = 0; j < DIMQ; j++) {
        float d = acc[tix(j, j)];
#pragma unroll
        for (int k = 0; k < j; k++) d = fmaf(-acc[tix(j, k)], acc[tix(j, k)], d);
        d = sqrtf(fmaxf(d, 1e-20f));
        acc[tix(j, j)] = d;
        float invd = 1.0f / d;
#pragma unroll
        for (int i = j + 1; i < DIMQ; i++) {
            float v = acc[tix(i, j)];
#pragma unroll
            for (int k = 0; k < j; k++) v = fmaf(-acc[tix(i, k)], acc[tix(j, k)], v);
            acc[tix(i, j)] = v * invd;
        }
    }

    // ---- columns u and 4+u of C ----
    float cu[DIMQ], cv[DIMQ];
#pragma unroll
    for (int a = 0; a < DIMQ; a++) {
        float x0 =            acc[tix(a, 0)];
        float x1 = (a >= 1) ? acc[tix(a, 1)] : 0.f;
        float x2 = (a >= 2) ? acc[tix(a, 2)] : 0.f;
        float x3 = (a >= 3) ? acc[tix(a, 3)] : 0.f;
        cu[a] = sel4(x0, x1, x2, x3, u);
        float y0 = (a >= 4) ? acc[tix(a, 4)] : 0.f;
        float y1 = (a >= 5) ? acc[tix(a, 5)] : 0.f;
        float y2 = (a >= 6) ? acc[tix(a, 6)] : 0.f;
        float y3 = (a >= 7) ? acc[tix(a, 7)] : 0.f;
        cv[a] = sel4(y0, y1, y2, y3, u);
    }

    // ---- Rows u (T) and 4+u (Bw) of M = C^T sigma C via symmetry ----
    float T[DIMQ], Bw[DIMQ];
    {
        float wu[DIMQ], wv[DIMQ];
#pragma unroll
        for (int a = 0; a < DIMQ; a++) {
            float su = 0.f, sv = 0.f;
#pragma unroll
            for (int bb = 0; bb < DIMQ; bb++) {
                float sab = (a >= bb) ? sig[tix(a, bb)] : sig[tix(bb, a)];
                su = fmaf(sab, cu[bb], su);
                sv = fmaf(sab, cv[bb], sv);
            }
            wu[a] = su; wv[a] = sv;
        }
#pragma unroll
        for (int j = 0; j < DIMQ; j++) {
            float tj = 0.f, bj = 0.f;
#pragma unroll
            for (int a = j; a < DIMQ; a++) {
                float caj = acc[tix(a, j)];
                tj = fmaf(caj, wu[a], tj);
                bj = fmaf(caj, wv[a], bj);
            }
            T[j] = tj; Bw[j] = bj;
        }
    }

    // ---- Parallel two-sided Jacobi (Brent-Luk tournament, position space) ----
    // Pairs always (pos u, pos 4+u). Position permutation per round:
    // new[0..7] = old[0,4,1,2,5,6,7,3] (order-7 cycle)
#pragma unroll
    for (int round = 0; round < NROUNDS; round++) {
        float app = sel4(T[0], T[1], T[2], T[3], u);
        float apq = sel4(T[4], T[5], T[6], T[7], u);
        float aqq = sel4(Bw[4], Bw[5], Bw[6], Bw[7], u);
        // inner rotation via cos(2phi): tan2phi = beta/tau, cos2phi >= 0 branch
        float tau  = 0.5f * (aqq - app);
        float beta = apq;
        float r2   = fmaf(tau, tau, beta * beta);
        float rinv = rsqrtf(r2);
        float cos2 = fabsf(tau) * rinv;
        float sin2 = beta * copysignf(rinv, tau);   // beta * sign(tau) / r
        float c2   = fmaf(0.5f, cos2, 0.5f);        // cos^2(phi)
        float cinv = rsqrtf(c2);
        float c    = c2 * cinv;                     // cos(phi)
        float s    = 0.5f * sin2 * cinv;            // sin(phi)
        bool ok = fabsf(beta) > 1e-20f;
        c = ok ? c : 1.f;
        s = ok ? s : 0.f;
        float cs[4], ss[4];
#pragma unroll
        for (int i = 0; i < 4; i++) {
            cs[i] = __shfl_sync(FULLM, c, i, 4);
            ss[i] = __shfl_sync(FULLM, s, i, 4);
        }
        // left transform
#pragma unroll
        for (int k = 0; k < DIMQ; k++) {
            float t0 = T[k], b0 = Bw[k];
            T[k]  = c * t0 - s * b0;
            Bw[k] = s * t0 + c * b0;
        }
        // right transform
#pragma unroll
        for (int i = 0; i < 4; i++) {
            float tp = T[i], tq = T[4 + i];
            T[i]     = cs[i] * tp - ss[i] * tq;
            T[4 + i] = ss[i] * tp + cs[i] * tq;
            float bp = Bw[i], bq = Bw[4 + i];
            Bw[i]     = cs[i] * bp - ss[i] * bq;
            Bw[4 + i] = ss[i] * bp + cs[i] * bq;
        }
        // row migration + column relabel (skip on last round: pure relabeling)
        if (round < NROUNDS - 1) {
            int srcT = (u == 0) ? 0 : (u - 1);
            int srcB = (u == 3) ? 3 : (u + 1);
            float nT[DIMQ], nB[DIMQ];
#pragma unroll
            for (int k = 0; k < DIMQ; k++) {
                float offT = (u == 0) ? Bw[k] : T[k];
                float rT = __shfl_sync(FULLM, offT, srcT, 4);
                nT[k] = (u == 0) ? T[k] : rT;
                float rB = __shfl_sync(FULLM, Bw[k], srcB, 4);
                nB[k] = (u == 3) ? T[k] : rB;
            }
            T[0] = nT[0]; T[1] = nT[4]; T[2] = nT[1]; T[3] = nT[2];
            T[4] = nT[5]; T[5] = nT[6]; T[6] = nT[7]; T[7] = nT[3];
            Bw[0] = nB[0]; Bw[1] = nB[4]; Bw[2] = nB[1]; Bw[3] = nB[2];
            Bw[4] = nB[5]; Bw[5] = nB[6]; Bw[6] = nB[7]; Bw[7] = nB[3];
        }
    }

    // diag entries in position space: (pos u, col u) and (pos 4+u, col 4+u)
    float d1 = sel4(T[0], T[1], T[2], T[3], u);
    float d2 = sel4(Bw[4], Bw[5], Bw[6], Bw[7], u);
    float f = sqrtf(fabsf(d1) + 1e-6f) + sqrtf(fabsf(d2) + 1e-6f);
    f += __shfl_xor_sync(FULLM, f, 1, 4);
    f += __shfl_xor_sync(FULLM, f, 2, 4);
    if (u == 0) {
        f = fminf(fmaxf(f, 0.f), 1.f);
        out[b] = -logf(fmaxf(f, 1e-8f));
    }
}

extern "C" void kernel_launch(void* const* d_in, const int* in_sizes, int n_in,
                              void* d_out, int out_size) {
    const int* contexts = (const int*)d_in[0];
    const int* targets  = (const int*)d_in[1];
    const float* emb    = (const float*)d_in[2];
    float* out = (float*)d_out;
    int B = in_sizes[1];
    int threads = 64;
    int total = B * 4;
    int blocks = (total + threads - 1) / threads;
    qcbow_kernel<<<blocks, threads>>>(contexts, targets, emb, out, B);
}

// round 14
// speedup vs baseline: 2.2435x; 1.0880x over previous
#include <cuda_runtime.h>
#include <math.h>

#define DIMQ 8
#define TRILQ 36
#define SEQ 10
#define NROUNDS 14   // exactly 2 tournament sweeps (7 rounds = 1 sweep)
#define FULLM 0xffffffffu

__device__ __forceinline__ constexpr int tix(int i, int j) { return i * (i + 1) / 2 + j; } // j<=i

__device__ __forceinline__ float sel4(float a, float b, float c, float d, int u) {
    float ab = (u & 1) ? b : a;
    float cd = (u & 1) ? d : c;
    return (u & 2) ? cd : ab;
}

// Compute density of one token's L and fold into dst.
__device__ __forceinline__ void accum_density(const float* __restrict__ row,
                                              float* dst, bool accumulate, bool gate) {
    float L[TRILQ];
    const float4* r4 = (const float4*)row;
#pragma unroll
    for (int q = 0; q < 9; q++) {
        float4 v = __ldg(r4 + q);
        L[4 * q + 0] = v.x; L[4 * q + 1] = v.y; L[4 * q + 2] = v.z; L[4 * q + 3] = v.w;
    }
#pragma unroll
    for (int i = 0; i < DIMQ; i++) L[tix(i, i)] = fmaxf(L[tix(i, i)], 1e-4f);
    // tr(L L^T) = ||L||_F^2 ; 4 partial accumulators to break the serial fma chain
    float t0 = 0.f, t1 = 0.f, t2 = 0.f, t3 = 0.f;
#pragma unroll
    for (int t = 0; t < TRILQ; t += 4) {
        t0 = fmaf(L[t + 0], L[t + 0], t0);
        t1 = fmaf(L[t + 1], L[t + 1], t1);
        t2 = fmaf(L[t + 2], L[t + 2], t2);
        t3 = fmaf(L[t + 3], L[t + 3], t3);
    }
    float tr = (t0 + t1) + (t2 + t3);
    // analytic: eig-shift corr is exactly 1e-6 -> rho = L L^T + 2e-6 I, denom = tr + 1.7e-5
    float inv = gate ? (1.0f / (tr + 1.7e-5f)) : 0.f;
#pragma unroll
    for (int i = 0; i < DIMQ; i++)
#pragma unroll
        for (int j = 0; j <= i; j++) {
            float sm = (i == j) ? 2e-6f : 0.f;
#pragma unroll
            for (int k = 0; k <= j; k++)
                sm = fmaf(L[tix(i, k)], L[tix(j, k)], sm);
            if (accumulate) dst[tix(i, j)] = fmaf(sm, inv, dst[tix(i, j)]);
            else            dst[tix(i, j)] = sm * inv;
        }
}

__global__ __launch_bounds__(64, 8) void qcbow_kernel(
    const int* __restrict__ contexts,
    const int* __restrict__ targets,
    const float* __restrict__ emb,
    float* __restrict__ out, int B)
{
    int tid = blockIdx.x * blockDim.x + threadIdx.x;
    int b = tid >> 2;       // element
    int u = tid & 3;        // lane within quad
    if (b >= B) return;

    float acc[TRILQ];
#pragma unroll
    for (int t = 0; t < TRILQ; t++) acc[t] = 0.f;
    float sig[TRILQ];
#pragma unroll
    for (int t = 0; t < TRILQ; t++) sig[t] = 0.f;
    float cnt = 0.f;

    // ---- Phase 1: token densities, split across the quad ----
#pragma unroll
    for (int r = 0; r < 3; r++) {
        int s = u + r * 4;
        if (s < SEQ) {
            int tok = __ldg(contexts + b * SEQ + s);
            bool gate = (tok != 0);
            accum_density(emb + (size_t)tok * TRILQ, acc, true, gate);
            cnt += gate ? 1.f : 0.f;
        }
    }
    if (u == 3) {
        int tok = __ldg(targets + b);
        accum_density(emb + (size_t)tok * TRILQ, sig, false, true);
    }

    // quad all-reduce of acc, cnt; broadcast sig from lane 3
#pragma unroll
    for (int t = 0; t < TRILQ; t++) {
        acc[t] += __shfl_xor_sync(FULLM, acc[t], 1, 4);
        acc[t] += __shfl_xor_sync(FULLM, acc[t], 2, 4);
    }
    cnt += __shfl_xor_sync(FULLM, cnt, 1, 4);
    cnt += __shfl_xor_sync(FULLM, cnt, 2, 4);
#pragma unroll
    for (int t = 0; t < TRILQ; t++) sig[t] = __shfl_sync(FULLM, sig[t], 3, 4);

    // ---- rho' = ctx_avg + 1e-6 I ; Cholesky in place (redundant per lane) ----
    float icnt = 1.0f / cnt;
#pragma unroll
    for (int t = 0; t < TRILQ; t++) acc[t] *= icnt;
#pragma unroll
    for (int i = 0; i < DIMQ; i++) acc[tix(i, i)] += 1e-6f;

#pragma unroll
    for (int j = 0; j < DIMQ; j++) {
        float dd = acc[tix(j, j)];
#pragma unroll
        for (int k = 0; k < j; k++) dd = fmaf(-acc[tix(j, k)], acc[tix(j, k)], dd);
        dd = fmaxf(dd, 1e-20f);
        float invd = rsqrtf(dd);        // 1 MUFU instead of sqrt + rcp
        acc[tix(j, j)] = dd * invd;     // = sqrt(dd)
#pragma unroll
        for (int i = j + 1; i < DIMQ; i++) {
            float v = acc[tix(i, j)];
#pragma unroll
            for (int k = 0; k < j; k++) v = fmaf(-acc[tix(i, k)], acc[tix(j, k)], v);
            acc[tix(i, j)] = v * invd;
        }
    }

    // ---- columns u and 4+u of C ----
    float cu[DIMQ], cv[DIMQ];
#pragma unroll
    for (int a = 0; a < DIMQ; a++) {
        float x0 =            acc[tix(a, 0)];
        float x1 = (a >= 1) ? acc[tix(a, 1)] : 0.f;
        float x2 = (a >= 2) ? acc[tix(a, 2)] : 0.f;
        float x3 = (a >= 3) ? acc[tix(a, 3)] : 0.f;
        cu[a] = sel4(x0, x1, x2, x3, u);
        float y0 = (a >= 4) ? acc[tix(a, 4)] : 0.f;
        float y1 = (a >= 5) ? acc[tix(a, 5)] : 0.f;
        float y2 = (a >= 6) ? acc[tix(a, 6)] : 0.f;
        float y3 = (a >= 7) ? acc[tix(a, 7)] : 0.f;
        cv[a] = sel4(y0, y1, y2, y3, u);
    }

    // ---- Rows u (T) and 4+u (Bw) of M = C^T sigma C via symmetry ----
    float T[DIMQ], Bw[DIMQ];
    {
        float wu[DIMQ], wv[DIMQ];
#pragma unroll
        for (int a = 0; a < DIMQ; a++) {
            float su = 0.f, sv = 0.f;
#pragma unroll
            for (int bb = 0; bb < DIMQ; bb++) {
                float sab = (a >= bb) ? sig[tix(a, bb)] : sig[tix(bb, a)];
                su = fmaf(sab, cu[bb], su);
                sv = fmaf(sab, cv[bb], sv);
            }
            wu[a] = su; wv[a] = sv;
        }
#pragma unroll
        for (int j = 0; j < DIMQ; j++) {
            float tj = 0.f, bj = 0.f;
#pragma unroll
            for (int a = j; a < DIMQ; a++) {
                float caj = acc[tix(a, j)];
                tj = fmaf(caj, wu[a], tj);
                bj = fmaf(caj, wv[a], bj);
            }
            T[j] = tj; Bw[j] = bj;
        }
    }

    // ---- Parallel two-sided Jacobi (Brent-Luk tournament, position space) ----
    // Pairs always (pos u, pos 4+u). Position permutation per round:
    // new[0..7] = old[0,4,1,2,5,6,7,3] (order-7 cycle)
#pragma unroll
    for (int round = 0; round < NROUNDS; round++) {
        float app = sel4(T[0], T[1], T[2], T[3], u);
        float apq = sel4(T[4], T[5], T[6], T[7], u);
        float aqq = sel4(Bw[4], Bw[5], Bw[6], Bw[7], u);
        // inner rotation via cos(2phi): tan2phi = beta/tau, cos2phi >= 0 branch
        float tau  = 0.5f * (aqq - app);
        float beta = apq;
        float r2   = fmaf(tau, tau, beta * beta);
        float rinv = rsqrtf(r2);
        float cos2 = fabsf(tau) * rinv;
        float sin2 = beta * copysignf(rinv, tau);   // beta * sign(tau) / r
        float c2   = fmaf(0.5f, cos2, 0.5f);        // cos^2(phi)
        float cinv = rsqrtf(c2);
        float c    = c2 * cinv;                     // cos(phi)
        float s    = 0.5f * sin2 * cinv;            // sin(phi)
        bool ok = fabsf(beta) > 1e-20f;
        c = ok ? c : 1.f;
        s = ok ? s : 0.f;
        float cs[4], ss[4];
#pragma unroll
        for (int i = 0; i < 4; i++) {
            cs[i] = __shfl_sync(FULLM, c, i, 4);
            ss[i] = __shfl_sync(FULLM, s, i, 4);
        }
        // left transform
#pragma unroll
        for (int k = 0; k < DIMQ; k++) {
            float t0 = T[k], b0 = Bw[k];
            T[k]  = c * t0 - s * b0;
            Bw[k] = s * t0 + c * b0;
        }
        // right transform
#pragma unroll
        for (int i = 0; i < 4; i++) {
            float tp = T[i], tq = T[4 + i];
            T[i]     = cs[i] * tp - ss[i] * tq;
            T[4 + i] = ss[i] * tp + cs[i] * tq;
            float bp = Bw[i], bq = Bw[4 + i];
            Bw[i]     = cs[i] * bp - ss[i] * bq;
            Bw[4 + i] = ss[i] * bp + cs[i] * bq;
        }
        // row migration + column relabel (skip on last round: pure relabeling)
        if (round < NROUNDS - 1) {
            int srcT = (u == 0) ? 0 : (u - 1);
            int srcB = (u == 3) ? 3 : (u + 1);
            float nT[DIMQ], nB[DIMQ];
#pragma unroll
            for (int k = 0; k < DIMQ; k++) {
                float offT = (u == 0) ? Bw[k] : T[k];
                float rT = __shfl_sync(FULLM, offT, srcT, 4);
                nT[k] = (u == 0) ? T[k] : rT;
                float rB = __shfl_sync(FULLM, Bw[k], srcB, 4);
                nB[k] = (u == 3) ? T[k] : rB;
            }
            T[0] = nT[0]; T[1] = nT[4]; T[2] = nT[1]; T[3] = nT[2];
            T[4] = nT[5]; T[5] = nT[6]; T[6] = nT[7]; T[7] = nT[3];
            Bw[0] = nB[0]; Bw[1] = nB[4]; Bw[2] = nB[1]; Bw[3] = nB[2];
            Bw[4] = nB[5]; Bw[5] = nB[6]; Bw[6] = nB[7]; Bw[7] = nB[3];
        }
    }

    // diag entries in position space: (pos u, col u) and (pos 4+u, col 4+u)
    float d1 = sel4(T[0], T[1], T[2], T[3], u);
    float d2 = sel4(Bw[4], Bw[5], Bw[6], Bw[7], u);
    float f = sqrtf(fabsf(d1) + 1e-6f) + sqrtf(fabsf(d2) + 1e-6f);
    f += __shfl_xor_sync(FULLM, f, 1, 4);
    f += __shfl_xor_sync(FULLM, f, 2, 4);
    if (u == 0) {
        f = fminf(fmaxf(f, 0.f), 1.f);
        out[b] = -logf(fmaxf(f, 1e-8f));
    }
}

extern "C" void kernel_launch(void* const* d_in, const int* in_sizes, int n_in,
                              void* d_out, int out_size) {
    const int* contexts = (const int*)d_in[0];
    const int* targets  = (const int*)d_in[1];
    const float* emb    = (const float*)d_in[2];
    float* out = (float*)d_out;
    int B = in_sizes[1];
    int threads = 64;
    int total = B * 4;
    int blocks = (total + threads - 1) / threads;
    qcbow_kernel<<<blocks, threads>>>(contexts, targets, emb, out, B);
}

// round 16
// speedup vs baseline: 2.2684x; 1.0111x over previous
#include <cuda_runtime.h>
#include <math.h>

#define DIMQ 8
#define TRILQ 36
#define SEQ 10
#define NFULLROUNDS 13   // 13 full rounds + 1 analytic diag-only finish = 14 rotation rounds (proven accurate)
#define FULLM 0xffffffffu

__device__ __forceinline__ constexpr int tix(int i, int j) { return i * (i + 1) / 2 + j; } // j<=i

__device__ __forceinline__ float sel4(float a, float b, float c, float d, int u) {
    float ab = (u & 1) ? b : a;
    float cd = (u & 1) ? d : c;
    return (u & 2) ? cd : ab;
}

// Compute density of one token's L and fold into dst.
__device__ __forceinline__ void accum_density(const float* __restrict__ row,
                                              float* dst, bool accumulate, bool gate) {
    float L[TRILQ];
    const float4* r4 = (const float4*)row;
#pragma unroll
    for (int q = 0; q < 9; q++) {
        float4 v = __ldg(r4 + q);
        L[4 * q + 0] = v.x; L[4 * q + 1] = v.y; L[4 * q + 2] = v.z; L[4 * q + 3] = v.w;
    }
#pragma unroll
    for (int i = 0; i < DIMQ; i++) L[tix(i, i)] = fmaxf(L[tix(i, i)], 1e-4f);
    // tr(L L^T) = ||L||_F^2 ; 4 partial accumulators to break the serial fma chain
    float t0 = 0.f, t1 = 0.f, t2 = 0.f, t3 = 0.f;
#pragma unroll
    for (int t = 0; t < TRILQ; t += 4) {
        t0 = fmaf(L[t + 0], L[t + 0], t0);
        t1 = fmaf(L[t + 1], L[t + 1], t1);
        t2 = fmaf(L[t + 2], L[t + 2], t2);
        t3 = fmaf(L[t + 3], L[t + 3], t3);
    }
    float tr = (t0 + t1) + (t2 + t3);
    // analytic: eig-shift corr is exactly 1e-6 -> rho = L L^T + 2e-6 I, denom = tr + 1.7e-5
    float inv = gate ? (1.0f / (tr + 1.7e-5f)) : 0.f;
#pragma unroll
    for (int i = 0; i < DIMQ; i++)
#pragma unroll
        for (int j = 0; j <= i; j++) {
            float sm = (i == j) ? 2e-6f : 0.f;
#pragma unroll
            for (int k = 0; k <= j; k++)
                sm = fmaf(L[tix(i, k)], L[tix(j, k)], sm);
            if (accumulate) dst[tix(i, j)] = fmaf(sm, inv, dst[tix(i, j)]);
            else            dst[tix(i, j)] = sm * inv;
        }
}

__global__ __launch_bounds__(64, 8) void qcbow_kernel(
    const int* __restrict__ contexts,
    const int* __restrict__ targets,
    const float* __restrict__ emb,
    float* __restrict__ out, int B)
{
    int tid = blockIdx.x * blockDim.x + threadIdx.x;
    int b = tid >> 2;       // element
    int u = tid & 3;        // lane within quad
    if (b >= B) return;

    float acc[TRILQ];
#pragma unroll
    for (int t = 0; t < TRILQ; t++) acc[t] = 0.f;
    float sig[TRILQ];
#pragma unroll
    for (int t = 0; t < TRILQ; t++) sig[t] = 0.f;
    float cnt = 0.f;

    // ---- Phase 1: token densities, split across the quad ----
#pragma unroll
    for (int r = 0; r < 3; r++) {
        int s = u + r * 4;
        if (s < SEQ) {
            int tok = __ldg(contexts + b * SEQ + s);
            bool gate = (tok != 0);
            accum_density(emb + (size_t)tok * TRILQ, acc, true, gate);
            cnt += gate ? 1.f : 0.f;
        }
    }
    if (u == 3) {
        int tok = __ldg(targets + b);
        accum_density(emb + (size_t)tok * TRILQ, sig, false, true);
    }

    // quad all-reduce of acc, cnt; broadcast sig from lane 3
#pragma unroll
    for (int t = 0; t < TRILQ; t++) {
        acc[t] += __shfl_xor_sync(FULLM, acc[t], 1, 4);
        acc[t] += __shfl_xor_sync(FULLM, acc[t], 2, 4);
    }
    cnt += __shfl_xor_sync(FULLM, cnt, 1, 4);
    cnt += __shfl_xor_sync(FULLM, cnt, 2, 4);
#pragma unroll
    for (int t = 0; t < TRILQ; t++) sig[t] = __shfl_sync(FULLM, sig[t], 3, 4);

    // ---- rho' = ctx_avg + 1e-6 I ; Cholesky in place (redundant per lane) ----
    float icnt = 1.0f / cnt;
#pragma unroll
    for (int t = 0; t < TRILQ; t++) acc[t] *= icnt;
#pragma unroll
    for (int i = 0; i < DIMQ; i++) acc[tix(i, i)] += 1e-6f;

#pragma unroll
    for (int j = 0; j < DIMQ; j++) {
        float dd = acc[tix(j, j)];
#pragma unroll
        for (int k = 0; k < j; k++) dd = fmaf(-acc[tix(j, k)], acc[tix(j, k)], dd);
        dd = fmaxf(dd, 1e-20f);
        float invd = rsqrtf(dd);        // 1 MUFU instead of sqrt + rcp
        acc[tix(j, j)] = dd * invd;     // = sqrt(dd)
#pragma unroll
        for (int i = j + 1; i < DIMQ; i++) {
            float v = acc[tix(i, j)];
#pragma unroll
            for (int k = 0; k < j; k++) v = fmaf(-acc[tix(i, k)], acc[tix(j, k)], v);
            acc[tix(i, j)] = v * invd;
        }
    }

    // ---- columns u and 4+u of C ----
    float cu[DIMQ], cv[DIMQ];
#pragma unroll
    for (int a = 0; a < DIMQ; a++) {
        float x0 =            acc[tix(a, 0)];
        float x1 = (a >= 1) ? acc[tix(a, 1)] : 0.f;
        float x2 = (a >= 2) ? acc[tix(a, 2)] : 0.f;
        float x3 = (a >= 3) ? acc[tix(a, 3)] : 0.f;
        cu[a] = sel4(x0, x1, x2, x3, u);
        float y0 = (a >= 4) ? acc[tix(a, 4)] : 0.f;
        float y1 = (a >= 5) ? acc[tix(a, 5)] : 0.f;
        float y2 = (a >= 6) ? acc[tix(a, 6)] : 0.f;
        float y3 = (a >= 7) ? acc[tix(a, 7)] : 0.f;
        cv[a] = sel4(y0, y1, y2, y3, u);
    }

    // ---- Rows u (T) and 4+u (Bw) of M = C^T sigma C via symmetry ----
    float T[DIMQ], Bw[DIMQ];
    {
        float wu[DIMQ], wv[DIMQ];
#pragma unroll
        for (int a = 0; a < DIMQ; a++) {
            float su = 0.f, sv = 0.f;
#pragma unroll
            for (int bb = 0; bb < DIMQ; bb++) {
                float sab = (a >= bb) ? sig[tix(a, bb)] : sig[tix(bb, a)];
                su = fmaf(sab, cu[bb], su);
                sv = fmaf(sab, cv[bb], sv);
            }
            wu[a] = su; wv[a] = sv;
        }
#pragma unroll
        for (int j = 0; j < DIMQ; j++) {
            float tj = 0.f, bj = 0.f;
#pragma unroll
            for (int a = j; a < DIMQ; a++) {
                float caj = acc[tix(a, j)];
                tj = fmaf(caj, wu[a], tj);
                bj = fmaf(caj, wv[a], bj);
            }
            T[j] = tj; Bw[j] = bj;
        }
    }

    // ---- Parallel two-sided Jacobi (Brent-Luk tournament, position space) ----
    // Pairs always (pos u, pos 4+u). Position permutation per round:
    // new[0..7] = old[0,4,1,2,5,6,7,3] (order-7 cycle)
#pragma unroll
    for (int round = 0; round < NFULLROUNDS; round++) {
        float app = sel4(T[0], T[1], T[2], T[3], u);
        float apq = sel4(T[4], T[5], T[6], T[7], u);
        float aqq = sel4(Bw[4], Bw[5], Bw[6], Bw[7], u);
        // inner rotation via cos(2phi): tan2phi = beta/tau, cos2phi >= 0 branch
        float tau  = 0.5f * (aqq - app);
        float beta = apq;
        float r2   = fmaf(tau, tau, beta * beta);
        float rinv = rsqrtf(r2);
        float cos2 = fabsf(tau) * rinv;
        float sin2 = beta * copysignf(rinv, tau);   // beta * sign(tau) / r
        float c2   = fmaf(0.5f, cos2, 0.5f);        // cos^2(phi)
        float cinv = rsqrtf(c2);
        float c    = c2 * cinv;                     // cos(phi)
        float s    = 0.5f * sin2 * cinv;            // sin(phi)
        bool ok = fabsf(beta) > 1e-20f;
        c = ok ? c : 1.f;
        s = ok ? s : 0.f;
        float cs[4], ss[4];
#pragma unroll
        for (int i = 0; i < 4; i++) {
            cs[i] = __shfl_sync(FULLM, c, i, 4);
            ss[i] = __shfl_sync(FULLM, s, i, 4);
        }
        // left transform
#pragma unroll
        for (int k = 0; k < DIMQ; k++) {
            float t0 = T[k], b0 = Bw[k];
            T[k]  = c * t0 - s * b0;
            Bw[k] = s * t0 + c * b0;
        }
        // right transform
#pragma unroll
        for (int i = 0; i < 4; i++) {
            float tp = T[i], tq = T[4 + i];
            T[i]     = cs[i] * tp - ss[i] * tq;
            T[4 + i] = ss[i] * tp + cs[i] * tq;
            float bp = Bw[i], bq = Bw[4 + i];
            Bw[i]     = cs[i] * bp - ss[i] * bq;
            Bw[4 + i] = ss[i] * bp + cs[i] * bq;
        }
        // row migration + column relabel
        {
            int srcT = (u == 0) ? 0 : (u - 1);
            int srcB = (u == 3) ? 3 : (u + 1);
            float nT[DIMQ], nB[DIMQ];
#pragma unroll
            for (int k = 0; k < DIMQ; k++) {
                float offT = (u == 0) ? Bw[k] : T[k];
                float rT = __shfl_sync(FULLM, offT, srcT, 4);
                nT[k] = (u == 0) ? T[k] : rT;
                float rB = __shfl_sync(FULLM, Bw[k], srcB, 4);
                nB[k] = (u == 3) ? T[k] : rB;
            }
            T[0] = nT[0]; T[1] = nT[4]; T[2] = nT[1]; T[3] = nT[2];
            T[4] = nT[5]; T[5] = nT[6]; T[6] = nT[7]; T[7] = nT[3];
            Bw[0] = nB[0]; Bw[1] = nB[4]; Bw[2] = nB[1]; Bw[3] = nB[2];
            Bw[4] = nB[5]; Bw[5] = nB[6]; Bw[6] = nB[7]; Bw[7] = nB[3];
        }
    }

    // ---- Analytic final round (round 14): each pair's diag closure needs only
    //      its own (app, apq, aqq):
    //      d1 = c2*app + s2*aqq - sin2*apq ; d2 = s2*app + c2*aqq + sin2*apq
    //      with c2=(1+cos2phi)/2, s2=(1-cos2phi)/2, sin2=sin(2phi).
    //      No shuffles, no row/col transforms, no migration.
    float d1, d2;
    {
        float app = sel4(T[0], T[1], T[2], T[3], u);
        float apq = sel4(T[4], T[5], T[6], T[7], u);
        float aqq = sel4(Bw[4], Bw[5], Bw[6], Bw[7], u);
        float tau  = 0.5f * (aqq - app);
        float beta = apq;
        float r2   = fmaf(tau, tau, beta * beta);
        float rinv = rsqrtf(r2);
        float cos2 = fabsf(tau) * rinv;             // cos(2phi)
        bool ok = fabsf(beta) > 1e-20f;
        cos2 = ok ? cos2 : 1.f;
        float sin2 = ok ? (beta * copysignf(rinv, tau)) : 0.f;   // sin(2phi)
        float c2   = fmaf(0.5f, cos2, 0.5f);
        float s2   = fmaf(-0.5f, cos2, 0.5f);
        d1 = c2 * app + s2 * aqq - sin2 * apq;
        d2 = s2 * app + c2 * aqq + sin2 * apq;
    }

    float f = sqrtf(fabsf(d1) + 1e-6f) + sqrtf(fabsf(d2) + 1e-6f);
    f += __shfl_xor_sync(FULLM, f, 1, 4);
    f += __shfl_xor_sync(FULLM, f, 2, 4);
    if (u == 0) {
        f = fminf(fmaxf(f, 0.f), 1.f);
        out[b] = -logf(fmaxf(f, 1e-8f));
    }
}

extern "C" void kernel_launch(void* const* d_in, const int* in_sizes, int n_in,
                              void* d_out, int out_size) {
    const int* contexts = (const int*)d_in[0];
    const int* targets  = (const int*)d_in[1];
    const float* emb    = (const float*)d_in[2];
    float* out = (float*)d_out;
    int B = in_sizes[1];
    int threads = 64;
    int total = B * 4;
    int blocks = (total + threads - 1) / threads;
    qcbow_kernel<<<blocks, threads>>>(contexts, targets, emb, out, B);
}